// round 17
// baseline (speedup 1.0000x reference)
#include <cuda_runtime.h>
#include <cstdint>

#define N_NODES   100000
#define N_EDGES   640000
#define IN_FEAT   128

#define SCORE_SCALE     2048.0f      // 2^11 fixed point
#define SCORE_INV_SCALE (1.0f / 2048.0f)

// Packed per-node scores: low int16 = src score, high int16 = trg score.
__device__ int g_score[N_NODES];

// ---------------------------------------------------------------------------
// Kernel 1: per-node dual dot products.
// 8 nodes per warp, 4 lanes per node. Each lane front-loads 8 independent
// float4s of its node's row (MLP=8, 128B in flight per thread), then FMAs
// against W (L1-resident loads inside the loop to cap register use).
// Butterfly reduction over 4 lanes: 2 stages x 2 = 4 SHFL per 8 nodes.
// ---------------------------------------------------------------------------
__global__ __launch_bounds__(512) void node_scores_kernel(
    const float* __restrict__ x,     // [N_NODES, 128]
    const float* __restrict__ W)     // [1, 256] = [W_src(128) | W_trg(128)]
{
    const int warp_in_block = threadIdx.x >> 5;
    const int lane          = threadIdx.x & 31;
    const int group         = lane >> 2;        // 0..7: which node in the warp
    const int sub           = lane & 3;         // 0..3: slot within the group

    const int w    = blockIdx.x * 16 + warp_in_block;
    const int node = 8 * w + group;
    if (node >= N_NODES) return;

    const float4* xr = reinterpret_cast<const float4*>(x + (size_t)node * IN_FEAT);
    const float4* w4 = reinterpret_cast<const float4*>(W);

    // Front-batch 8 independent row loads (slots sub + 4k).
    float4 xv[8];
    #pragma unroll
    for (int k = 0; k < 8; ++k)
        xv[k] = __ldg(xr + sub + 4 * k);

    // FMA against W; W loads are L1-hits, issued inside the loop.
    float ss = 0.0f, st = 0.0f;
    #pragma unroll
    for (int k = 0; k < 8; ++k) {
        const float4 ws = __ldg(w4 + sub + 4 * k);
        const float4 wt = __ldg(w4 + 32 + sub + 4 * k);
        ss += xv[k].x * ws.x + xv[k].y * ws.y + xv[k].z * ws.z + xv[k].w * ws.w;
        st += xv[k].x * wt.x + xv[k].y * wt.y + xv[k].z * wt.z + xv[k].w * wt.w;
    }

    // Butterfly over the 4-lane group.
    #pragma unroll
    for (int off = 2; off > 0; off >>= 1) {
        ss += __shfl_xor_sync(0xFFFFFFFFu, ss, off);
        st += __shfl_xor_sync(0xFFFFFFFFu, st, off);
    }

    if (sub == 0) {
        const int si = __float2int_rn(fminf(fmaxf(ss * SCORE_SCALE, -32767.0f), 32767.0f));
        const int ti = __float2int_rn(fminf(fmaxf(st * SCORE_SCALE, -32767.0f), 32767.0f));
        g_score[node] = (si & 0xFFFF) | (ti << 16);
    }
}

// ---------------------------------------------------------------------------
// Kernel 2 (champion, R5): per-edge gather + sigmoid, 4 edges per thread.
// Two random 4B gathers per edge into ONE 400KB packed table.
// ---------------------------------------------------------------------------
__global__ __launch_bounds__(256) void edge_sigmoid_kernel(
    const int*   __restrict__ edge_src,
    const int*   __restrict__ edge_trg,
    const float* __restrict__ b,
    float*       __restrict__ out)
{
    const int g = blockIdx.x * blockDim.x + threadIdx.x;   // group of 4 edges
    if (g * 4 >= N_EDGES) return;

    const float bias = __ldg(b);

    const int4 s4 = __ldg(reinterpret_cast<const int4*>(edge_src) + g);
    const int4 t4 = __ldg(reinterpret_cast<const int4*>(edge_trg) + g);

    // Issue all 8 gathers before consuming.
    const int ps0 = g_score[s4.x], ps1 = g_score[s4.y];
    const int ps2 = g_score[s4.z], ps3 = g_score[s4.w];
    const int pt0 = g_score[t4.x], pt1 = g_score[t4.y];
    const int pt2 = g_score[t4.z], pt3 = g_score[t4.w];

    float4 r;
    {
        float z;
        z = (float)((short)ps0 + (pt0 >> 16)) * SCORE_INV_SCALE + bias;
        r.x = 1.0f / (1.0f + __expf(-z));
        z = (float)((short)ps1 + (pt1 >> 16)) * SCORE_INV_SCALE + bias;
        r.y = 1.0f / (1.0f + __expf(-z));
        z = (float)((short)ps2 + (pt2 >> 16)) * SCORE_INV_SCALE + bias;
        r.z = 1.0f / (1.0f + __expf(-z));
        z = (float)((short)ps3 + (pt3 >> 16)) * SCORE_INV_SCALE + bias;
        r.w = 1.0f / (1.0f + __expf(-z));
    }
    reinterpret_cast<float4*>(out)[g] = r;
}

// ---------------------------------------------------------------------------
extern "C" void kernel_launch(void* const* d_in, const int* in_sizes, int n_in,
                              void* d_out, int out_size)
{
    // Identify inputs defensively by element count.
    const float* x  = nullptr;
    const int*   es = nullptr;
    const int*   et = nullptr;
    const float* W  = nullptr;
    const float* b  = nullptr;

    for (int i = 0; i < n_in; ++i) {
        const int n = in_sizes[i];
        if (n == N_NODES * IN_FEAT)      x = (const float*)d_in[i];
        else if (n == N_EDGES) {
            if (!es) es = (const int*)d_in[i];
            else     et = (const int*)d_in[i];
        }
        else if (n == 2 * IN_FEAT)       W = (const float*)d_in[i];
        else if (n == 1)                 b = (const float*)d_in[i];
    }

    float* out = (float*)d_out;

    // Kernel 1: 16 warps/block, 8 nodes/warp -> 128 nodes/block
    const int blocks1 = (N_NODES + 127) / 128;
    node_scores_kernel<<<blocks1, 512>>>(x, W);

    // Kernel 2: 4 edges per thread -> 160K threads
    const int threads2 = N_EDGES / 4;                 // divides exactly
    const int blocks2  = (threads2 + 255) / 256;
    edge_sigmoid_kernel<<<blocks2, 256>>>(es, et, b, out);
}